// round 15
// baseline (speedup 1.0000x reference)
#include <cuda_runtime.h>
#include <cuda_bf16.h>
#include <cstdint>

// ---------------- problem constants ----------------
#define NN   4096
#define DD   128
#define EE   131072
#define HIDD 16
#define HH   8
#define HDD  16
#define SPLITS 4   // attention split-K

// ---------------- device scratch (no allocations allowed) ----------------
__device__ float g_deg[NN];
__device__ float g_dis[NN];
__device__ float g_agg[NN * DD];
__device__ float g_feat[NN * 1024];          // featurizations (max N x 128*8)
__device__ float g_h1[NN * HIDD];
__device__ float g_hlocal[NN * DD];
__device__ float g_tmp[NN * DD];
__device__ float g_h[NN * DD];
__device__ float g_qkv[NN * 384];
__device__ float g_part[HH * SPLITS * NN * 20];
__device__ float g_wpack[512 * 384];

// ---------------- B-spline basis (Cox–de Boor, matches reference exactly) ----------------
template<int GG, int KD>
__device__ __forceinline__ void bspline(float x, float* o) {
    constexpr float h  = 2.0f / GG;
    constexpr int  N0  = GG + 2 * KD;   // degree-0 interval count
    float b[N0];
#pragma unroll
    for (int j = 0; j < N0; j++) {
        float gj  = (j     - KD) * h - 1.0f;
        float gj1 = (j + 1 - KD) * h - 1.0f;
        b[j] = (x >= gj && x < gj1) ? 1.0f : 0.0f;
    }
#pragma unroll
    for (int jd = 1; jd <= KD; jd++) {
        const float inv = 1.0f / (jd * h);
#pragma unroll
        for (int m = 0; m + jd < N0; m++) {
            float gm  = (m          - KD) * h - 1.0f;
            float gm1 = (m + jd + 1 - KD) * h - 1.0f;
            b[m] = (x - gm) * inv * b[m] + (gm1 - x) * inv * b[m + 1];
        }
    }
#pragma unroll
    for (int j = 0; j < GG + KD; j++) o[j] = b[j];
}

// ---------------- featurization: [base, B_0..B_{NB-1}] per scalar ----------------
template<int GG, int KD, bool SILU>
__global__ void feat_kernel(const float* __restrict__ in, float* __restrict__ out, int total) {
    constexpr int NB = GG + KD;
    constexpr int F  = NB + 1;          // 8 or 4
    int idx = blockIdx.x * blockDim.x + threadIdx.x;
    if (idx >= total) return;
    float v = in[idx];
    float f[F];
    f[0] = SILU ? (v / (1.0f + __expf(-v))) : v;
    bspline<GG, KD>(v, f + 1);
    float4* o = (float4*)(out + (size_t)idx * F);
#pragma unroll
    for (int j = 0; j < F / 4; j++)
        o[j] = make_float4(f[4 * j], f[4 * j + 1], f[4 * j + 2], f[4 * j + 3]);
}

// ---------------- pack KAN weights into a GEMM-ready [IN*F, ldw] matrix ----------------
__global__ void pack_kan(const float* __restrict__ bw, const float* __restrict__ sw,
                         float* __restrict__ W, int IN, int OUT, int NB, int ldw, int ocol) {
    int t = blockIdx.x * blockDim.x + threadIdx.x;
    if (t >= IN * OUT) return;
    int o = t % OUT, i = t / OUT;
    int F = NB + 1;
    W[(size_t)(i * F) * ldw + ocol + o] = bw[(size_t)o * IN + i];
    for (int g = 0; g < NB; g++)
        W[(size_t)(i * F + 1 + g) * ldw + ocol + o] = sw[((size_t)o * IN + i) * NB + g];
}

// ---------------- tiled SGEMM: C[M,Nd] = A[M,K] @ W[K,Nd] ----------------
template<int BM, int BN, int BK, int TM, int TN>
__global__ void sgemm(const float* __restrict__ A, const float* __restrict__ W,
                      float* __restrict__ C, int M, int Kdim, int Nd) {
    __shared__ float As[BK][BM + 4];
    __shared__ float Ws[BK][BN];
    constexpr int NT = (BM / TM) * (BN / TN);
    const int tid = threadIdx.x;
    const int cx = tid % (BN / TN);
    const int ry = tid / (BN / TN);
    const int m0 = blockIdx.x * BM, n0 = blockIdx.y * BN;
    float acc[TM][TN];
#pragma unroll
    for (int u = 0; u < TM; u++)
#pragma unroll
        for (int v = 0; v < TN; v++) acc[u][v] = 0.0f;

    for (int k0 = 0; k0 < Kdim; k0 += BK) {
#pragma unroll
        for (int i = tid; i < BM * BK; i += NT) {
            int m = i / BK, k = i % BK;
            As[k][m] = A[(size_t)(m0 + m) * Kdim + k0 + k];
        }
#pragma unroll
        for (int i = tid; i < BK * BN; i += NT) {
            int k = i / BN, n = i % BN;
            Ws[k][n] = W[(size_t)(k0 + k) * Nd + n0 + n];
        }
        __syncthreads();
#pragma unroll
        for (int kk = 0; kk < BK; kk++) {
            float4 a4 = *(const float4*)&As[kk][ry * TM];
            float a[4] = {a4.x, a4.y, a4.z, a4.w};
            if constexpr (TN == 4) {
                float4 b4 = *(const float4*)&Ws[kk][cx * TN];
                float b[4] = {b4.x, b4.y, b4.z, b4.w};
#pragma unroll
                for (int u = 0; u < TM; u++)
#pragma unroll
                    for (int v = 0; v < TN; v++) acc[u][v] = fmaf(a[u], b[v], acc[u][v]);
            } else {
                float bs = Ws[kk][cx];
#pragma unroll
                for (int u = 0; u < TM; u++) acc[u][0] = fmaf(a[u], bs, acc[u][0]);
            }
        }
        __syncthreads();
    }
#pragma unroll
    for (int u = 0; u < TM; u++) {
        if constexpr (TN == 4) {
            *(float4*)&C[(size_t)(m0 + ry * TM + u) * Nd + n0 + cx * TN] =
                make_float4(acc[u][0], acc[u][1], acc[u][2], acc[u][3]);
        } else {
            C[(size_t)(m0 + ry * TM + u) * Nd + n0 + cx] = acc[u][0];
        }
    }
}

// ---------------- GCN helpers ----------------
__global__ void deg_init_k() {
    int i = blockIdx.x * blockDim.x + threadIdx.x;
    if (i < NN) g_deg[i] = 1.0f;  // self loop
}
__global__ void deg_scatter_k(const int* __restrict__ ei) {
    int e = blockIdx.x * blockDim.x + threadIdx.x;
    if (e < EE) atomicAdd(&g_deg[ei[e]], 1.0f);
}
__global__ void dis_k() {
    int i = blockIdx.x * blockDim.x + threadIdx.x;
    if (i < NN) {
        float d = g_deg[i];
        g_dis[i] = (d > 0.0f) ? rsqrtf(d) : 0.0f;
    }
}
__global__ void agg_init_k(const float* __restrict__ x) {
    int t = blockIdx.x * blockDim.x + threadIdx.x;
    if (t >= NN * DD) return;
    int n = t >> 7;
    float d = g_dis[n];
    g_agg[t] = d * d * x[t];
}
__global__ void edge_scatter_k(const int* __restrict__ ei, const float* __restrict__ x) {
    int gid = blockIdx.x * blockDim.x + threadIdx.x;
    int e = gid >> 5, lane = gid & 31;
    if (e >= EE) return;
    int r = ei[e], c = ei[EE + e];
    float w = g_dis[r] * g_dis[c];
    float4 xv = *(const float4*)(x + (size_t)r * DD + lane * 4);
    float* dst = g_agg + (size_t)c * DD + lane * 4;
    atomicAdd(dst + 0, w * xv.x);
    atomicAdd(dst + 1, w * xv.y);
    atomicAdd(dst + 2, w * xv.z);
    atomicAdd(dst + 3, w * xv.w);
}

// ---------------- layer norm (one warp per row): out = extra + LN(a+b)*s + bias ----------------
__global__ void ln_kernel(const float* __restrict__ a, const float* __restrict__ b,
                          const float* __restrict__ s, const float* __restrict__ bias,
                          const float* __restrict__ extra, float* __restrict__ out) {
    int gid = blockIdx.x * blockDim.x + threadIdx.x;
    int row = gid >> 5, lane = gid & 31;
    if (row >= NN) return;
    float4 av = *(const float4*)(a + (size_t)row * DD + lane * 4);
    float4 bv = *(const float4*)(b + (size_t)row * DD + lane * 4);
    float v0 = av.x + bv.x, v1 = av.y + bv.y, v2 = av.z + bv.z, v3 = av.w + bv.w;
    float sum = v0 + v1 + v2 + v3;
    float sq  = v0 * v0 + v1 * v1 + v2 * v2 + v3 * v3;
#pragma unroll
    for (int o = 16; o; o >>= 1) {
        sum += __shfl_xor_sync(0xffffffffu, sum, o);
        sq  += __shfl_xor_sync(0xffffffffu, sq,  o);
    }
    float mean = sum * (1.0f / 128.0f);
    float var  = sq * (1.0f / 128.0f) - mean * mean;
    float r = rsqrtf(var + 1e-5f);
    float4 sv = *(const float4*)(s + lane * 4);
    float4 bb = *(const float4*)(bias + lane * 4);
    float4 ev = make_float4(0.f, 0.f, 0.f, 0.f);
    if (extra) ev = *(const float4*)(extra + (size_t)row * DD + lane * 4);
    float4 ov;
    ov.x = (v0 - mean) * r * sv.x + bb.x + ev.x;
    ov.y = (v1 - mean) * r * sv.y + bb.y + ev.y;
    ov.z = (v2 - mean) * r * sv.z + bb.z + ev.z;
    ov.w = (v3 - mean) * r * sv.w + bb.w + ev.w;
    *(float4*)(out + (size_t)row * DD + lane * 4) = ov;
}

// ---------------- flash attention (split-K, one query row per thread) ----------------
__global__ void attn_kernel(const float* __restrict__ qkv, float* __restrict__ part) {
    const int n  = blockIdx.x * 128 + threadIdx.x;
    const int h  = blockIdx.y;
    const int sp = blockIdx.z;
    __shared__ float Ks[128][16];
    __shared__ float Vs[128][16];

    const float* qp = qkv + (size_t)n * 384 + h * HDD;
    float4 q0 = *(const float4*)(qp + 0);
    float4 q1 = *(const float4*)(qp + 4);
    float4 q2 = *(const float4*)(qp + 8);
    float4 q3 = *(const float4*)(qp + 12);

    float acc[16];
#pragma unroll
    for (int d = 0; d < 16; d++) acc[d] = 0.0f;
    float mrun = -1e30f, lrun = 0.0f;

    const int m0base = sp * (NN / SPLITS);
    for (int kt = 0; kt < NN / SPLITS; kt += 128) {
        int mrow = m0base + kt + threadIdx.x;
        const float* kp = qkv + (size_t)mrow * 384 + 128 + h * HDD;
        const float* vp = qkv + (size_t)mrow * 384 + 256 + h * HDD;
        *(float4*)&Ks[threadIdx.x][0]  = *(const float4*)(kp + 0);
        *(float4*)&Ks[threadIdx.x][4]  = *(const float4*)(kp + 4);
        *(float4*)&Ks[threadIdx.x][8]  = *(const float4*)(kp + 8);
        *(float4*)&Ks[threadIdx.x][12] = *(const float4*)(kp + 12);
        *(float4*)&Vs[threadIdx.x][0]  = *(const float4*)(vp + 0);
        *(float4*)&Vs[threadIdx.x][4]  = *(const float4*)(vp + 4);
        *(float4*)&Vs[threadIdx.x][8]  = *(const float4*)(vp + 8);
        *(float4*)&Vs[threadIdx.x][12] = *(const float4*)(vp + 12);
        __syncthreads();
#pragma unroll 2
        for (int mm = 0; mm < 128; mm++) {
            float4 k0 = *(const float4*)&Ks[mm][0];
            float4 k1 = *(const float4*)&Ks[mm][4];
            float4 k2 = *(const float4*)&Ks[mm][8];
            float4 k3 = *(const float4*)&Ks[mm][12];
            float s0 = fmaf(q0.x, k0.x, fmaf(q0.y, k0.y, fmaf(q0.z, k0.z, q0.w * k0.w)));
            float s1 = fmaf(q1.x, k1.x, fmaf(q1.y, k1.y, fmaf(q1.z, k1.z, q1.w * k1.w)));
            float s2 = fmaf(q2.x, k2.x, fmaf(q2.y, k2.y, fmaf(q2.z, k2.z, q2.w * k2.w)));
            float s3 = fmaf(q3.x, k3.x, fmaf(q3.y, k3.y, fmaf(q3.z, k3.z, q3.w * k3.w)));
            float s = ((s0 + s1) + (s2 + s3)) * 0.25f;
            if (s > mrun) {
                float c = __expf(mrun - s);
                lrun *= c;
#pragma unroll
                for (int d = 0; d < 16; d++) acc[d] *= c;
                mrun = s;
            }
            float p = __expf(s - mrun);
            lrun += p;
            float4 v0 = *(const float4*)&Vs[mm][0];
            float4 v1 = *(const float4*)&Vs[mm][4];
            float4 v2 = *(const float4*)&Vs[mm][8];
            float4 v3 = *(const float4*)&Vs[mm][12];
            acc[0]  = fmaf(p, v0.x, acc[0]);  acc[1]  = fmaf(p, v0.y, acc[1]);
            acc[2]  = fmaf(p, v0.z, acc[2]);  acc[3]  = fmaf(p, v0.w, acc[3]);
            acc[4]  = fmaf(p, v1.x, acc[4]);  acc[5]  = fmaf(p, v1.y, acc[5]);
            acc[6]  = fmaf(p, v1.z, acc[6]);  acc[7]  = fmaf(p, v1.w, acc[7]);
            acc[8]  = fmaf(p, v2.x, acc[8]);  acc[9]  = fmaf(p, v2.y, acc[9]);
            acc[10] = fmaf(p, v2.z, acc[10]); acc[11] = fmaf(p, v2.w, acc[11]);
            acc[12] = fmaf(p, v3.x, acc[12]); acc[13] = fmaf(p, v3.y, acc[13]);
            acc[14] = fmaf(p, v3.z, acc[14]); acc[15] = fmaf(p, v3.w, acc[15]);
        }
        __syncthreads();
    }
    float* pp = part + ((size_t)(h * SPLITS + sp) * NN + n) * 20;
#pragma unroll
    for (int d = 0; d < 16; d++) pp[d] = acc[d];
    pp[16] = mrun;
    pp[17] = lrun;
}

__global__ void attn_combine_k(const float* __restrict__ part, float* __restrict__ out) {
    int t = blockIdx.x * blockDim.x + threadIdx.x;
    if (t >= NN * HH) return;
    int n = t / HH, h = t % HH;
    float ms[SPLITS];
    float mstar = -1e30f;
#pragma unroll
    for (int sp = 0; sp < SPLITS; sp++) {
        ms[sp] = part[((size_t)(h * SPLITS + sp) * NN + n) * 20 + 16];
        mstar = fmaxf(mstar, ms[sp]);
    }
    float num[16];
#pragma unroll
    for (int d = 0; d < 16; d++) num[d] = 0.0f;
    float den = 0.0f;
#pragma unroll
    for (int sp = 0; sp < SPLITS; sp++) {
        const float* pp = part + ((size_t)(h * SPLITS + sp) * NN + n) * 20;
        float w = __expf(ms[sp] - mstar);
        den = fmaf(w, pp[17], den);
#pragma unroll
        for (int d = 0; d < 16; d++) num[d] = fmaf(w, pp[d], num[d]);
    }
    float inv = 1.0f / den;
    float* op = out + (size_t)n * DD + h * HDD;
#pragma unroll
    for (int d = 0; d < 16; d++) op[d] = num[d] * inv;
}

// ---------------- host orchestration ----------------
static inline float* symaddr(const void* sym) {
    void* p = nullptr;
    cudaGetSymbolAddress(&p, sym);
    return (float*)p;
}

extern "C" void kernel_launch(void* const* d_in, const int* in_sizes, int n_in,
                              void* d_out, int out_size) {
    const float* x       = (const float*)d_in[0];
    const int*   ei      = (const int*)d_in[1];
    const float* gcn_bw1 = (const float*)d_in[2];
    const float* gcn_sw1 = (const float*)d_in[3];
    const float* gcn_bw2 = (const float*)d_in[4];
    const float* gcn_sw2 = (const float*)d_in[5];
    const float* q_bw    = (const float*)d_in[6];
    const float* q_sw    = (const float*)d_in[7];
    const float* k_bw    = (const float*)d_in[8];
    const float* k_sw    = (const float*)d_in[9];
    const float* v_bw    = (const float*)d_in[10];
    const float* v_sw    = (const float*)d_in[11];
    const float* ffn_bw1 = (const float*)d_in[12];
    const float* ffn_sw1 = (const float*)d_in[13];
    const float* ffn_bw2 = (const float*)d_in[14];
    const float* ffn_sw2 = (const float*)d_in[15];
    const float* ln1_s   = (const float*)d_in[16];
    const float* ln1_b   = (const float*)d_in[17];
    const float* ln2_s   = (const float*)d_in[18];
    const float* ln2_b   = (const float*)d_in[19];
    const float* ln3_s   = (const float*)d_in[20];
    const float* ln3_b   = (const float*)d_in[21];
    float* out = (float*)d_out;

    float* p_agg    = symaddr(g_agg);
    float* p_feat   = symaddr(g_feat);
    float* p_h1     = symaddr(g_h1);
    float* p_hlocal = symaddr(g_hlocal);
    float* p_tmp    = symaddr(g_tmp);
    float* p_h      = symaddr(g_h);
    float* p_qkv    = symaddr(g_qkv);
    float* p_part   = symaddr(g_part);
    float* p_w      = symaddr(g_wpack);

    // ---- GCN aggregation ----
    deg_init_k<<<NN / 256, 256>>>();
    deg_scatter_k<<<EE / 256, 256>>>(ei);
    dis_k<<<NN / 256, 256>>>();
    agg_init_k<<<NN * DD / 256, 256>>>(x);
    edge_scatter_k<<<(EE * 32) / 256, 256>>>(ei, x);

    // ---- GCN ekan2: D->HID->D ----
    feat_kernel<4, 3, true><<<NN * DD / 256, 256>>>(p_agg, p_feat, NN * DD);
    pack_kan<<<(DD * HIDD + 255) / 256, 256>>>(gcn_bw1, gcn_sw1, p_w, DD, HIDD, 7, HIDD, 0);
    sgemm<64, 16, 16, 4, 1><<<dim3(NN / 64, 1), 256>>>(p_feat, p_w, p_h1, NN, DD * 8, HIDD);
    feat_kernel<4, 3, true><<<NN * HIDD / 256, 256>>>(p_h1, p_feat, NN * HIDD);
    pack_kan<<<(HIDD * DD + 255) / 256, 256>>>(gcn_bw2, gcn_sw2, p_w, HIDD, DD, 7, DD, 0);
    sgemm<64, 64, 16, 4, 4><<<dim3(NN / 64, DD / 64), 256>>>(p_feat, p_w, p_tmp, NN, HIDD * 8, DD);
    ln_kernel<<<NN * 32 / 256, 256>>>(x, p_tmp, ln1_s, ln1_b, nullptr, p_hlocal);

    // ---- QKV projections (shared featurization, fused GEMM N=384) ----
    feat_kernel<2, 1, false><<<NN * DD / 256, 256>>>(x, p_feat, NN * DD);
    pack_kan<<<(DD * DD + 255) / 256, 256>>>(q_bw, q_sw, p_w, DD, DD, 3, 384, 0);
    pack_kan<<<(DD * DD + 255) / 256, 256>>>(k_bw, k_sw, p_w, DD, DD, 3, 384, 128);
    pack_kan<<<(DD * DD + 255) / 256, 256>>>(v_bw, v_sw, p_w, DD, DD, 3, 384, 256);
    sgemm<64, 64, 16, 4, 4><<<dim3(NN / 64, 384 / 64), 256>>>(p_feat, p_w, p_qkv, NN, DD * 4, 384);

    // ---- attention (split-K flash + combine) ----
    attn_kernel<<<dim3(NN / 128, HH, SPLITS), 128>>>(p_qkv, p_part);
    attn_combine_k<<<(NN * HH) / 256, 256>>>(p_part, p_tmp);
    ln_kernel<<<NN * 32 / 256, 256>>>(x, p_tmp, ln2_s, ln2_b, p_hlocal, p_h);

    // ---- FFN ekan2: D->HID->D on h ----
    feat_kernel<4, 3, true><<<NN * DD / 256, 256>>>(p_h, p_feat, NN * DD);
    pack_kan<<<(DD * HIDD + 255) / 256, 256>>>(ffn_bw1, ffn_sw1, p_w, DD, HIDD, 7, HIDD, 0);
    sgemm<64, 16, 16, 4, 1><<<dim3(NN / 64, 1), 256>>>(p_feat, p_w, p_h1, NN, DD * 8, HIDD);
    feat_kernel<4, 3, true><<<NN * HIDD / 256, 256>>>(p_h1, p_feat, NN * HIDD);
    pack_kan<<<(HIDD * DD + 255) / 256, 256>>>(ffn_bw2, ffn_sw2, p_w, HIDD, DD, 7, DD, 0);
    sgemm<64, 64, 16, 4, 4><<<dim3(NN / 64, DD / 64), 256>>>(p_feat, p_w, p_tmp, NN, HIDD * 8, DD);

    // ---- final LN -> output ----
    ln_kernel<<<NN * 32 / 256, 256>>>(p_h, p_tmp, ln3_s, ln3_b, nullptr, out);
}